// round 15
// baseline (speedup 1.0000x reference)
#include <cuda_runtime.h>

#define Lc 1024
#define Bc 256
#define Dc 256
#define Tc 50
#define Hc 8
#define DHc 32

#define MEAN_CH 16  // L-chunks for mean pass
#define FL_CH 16    // L-chunks for flash pass (64 rows each)

// Scratch (allocation-free rule: __device__ globals)
__device__ float g_hbar_part[MEAN_CH][Bc*Dc];
__device__ float g_ctx[Bc*3*Dc];                // [b][0..767]
__device__ float g_qk[Bc*Hc*Dc];                // [b][h][i], includes 1/sqrt(32)
__device__ float g_wE_part[FL_CH][Bc*Hc*Dc];    // unnormalized partial [b][h][i]
__device__ float2 g_ms[Bc*FL_CH*Hc];            // (m, s) per (b, chunk, h)
__device__ float g_ho[Bc*Dc];                   // head_out flattened
__device__ float g_qk2[Bc*Dc];                  // includes 1/16
__device__ float g_fs[Bc*Lc];                   // [b][l]
__device__ float g_Wt1[Dc*Dc];                  // Wo1 @ Wq2
__device__ float g_Wcombo[Dc*Dc];               // (Wo1 @ Wq2 @ Wk2^T) / 16

__device__ __forceinline__ unsigned long long f2ull(float x, float y) {
    unsigned long long u;
    asm("mov.b64 %0, {%1,%2};" : "=l"(u) : "f"(x), "f"(y));
    return u;
}
__device__ __forceinline__ float2 ull2f2(unsigned long long u) {
    float2 f;
    asm("mov.b64 {%0,%1}, %2;" : "=f"(f.x), "=f"(f.y) : "l"(u));
    return f;
}
__device__ __forceinline__ void fma2(unsigned long long& acc, unsigned long long a, unsigned long long b) {
    asm("fma.rn.f32x2 %0, %1, %2, %3;" : "=l"(acc) : "l"(a), "l"(b), "l"(acc));
}
__device__ __forceinline__ void cp_async16(unsigned int saddr, const void* g) {
    asm volatile("cp.async.cg.shared.global [%0], [%1], 16;" :: "r"(saddr), "l"(g));
}

// 8-value fold reduction: lanes with lane%4==0 hold full sum for head (lane>>2). 9 shuffles.
__device__ __forceinline__ float fold8(const float sc[8], int lane) {
    bool hi16 = (lane & 16) != 0;
    float n[4];
    #pragma unroll
    for (int k = 0; k < 4; k++) {
        float give = hi16 ? sc[k] : sc[4 + k];
        float keep = hi16 ? sc[4 + k] : sc[k];
        n[k] = keep + __shfl_xor_sync(0xffffffffu, give, 16);
    }
    bool hi8 = (lane & 8) != 0;
    float m[2];
    #pragma unroll
    for (int j = 0; j < 2; j++) {
        float give = hi8 ? n[j] : n[2 + j];
        float keep = hi8 ? n[2 + j] : n[j];
        m[j] = keep + __shfl_xor_sync(0xffffffffu, give, 8);
    }
    bool hi4 = (lane & 4) != 0;
    float give = hi4 ? m[0] : m[1];
    float keep = hi4 ? m[1] : m[0];
    float v = keep + __shfl_xor_sync(0xffffffffu, give, 4);
    v += __shfl_xor_sync(0xffffffffu, v, 1);
    v += __shfl_xor_sync(0xffffffffu, v, 2);
    return v;
}

// 4-value fold: lanes with lane%8==0 hold row (lane>>3).
__device__ __forceinline__ float fold4(const float r[4], int lane) {
    bool hi16 = (lane & 16) != 0;
    float n[2];
    #pragma unroll
    for (int j = 0; j < 2; j++) {
        float give = hi16 ? r[j] : r[2 + j];
        float keep = hi16 ? r[2 + j] : r[j];
        n[j] = keep + __shfl_xor_sync(0xffffffffu, give, 16);
    }
    bool hi8 = (lane & 8) != 0;
    float give = hi8 ? n[0] : n[1];
    float keep = hi8 ? n[1] : n[0];
    float v = keep + __shfl_xor_sync(0xffffffffu, give, 8);
    v += __shfl_xor_sync(0xffffffffu, v, 4);
    v += __shfl_xor_sync(0xffffffffu, v, 2);
    v += __shfl_xor_sync(0xffffffffu, v, 1);
    return v;
}

// ---------------- 16x32-tile GEMM with register-prefetched K-tiles, 128 threads ----------------
template<int TRANSB>
__global__ void __launch_bounds__(128) k_gemm16(const float* __restrict__ A, int lda, int aSz,
                                                const float* __restrict__ B, int ldb, int bSz,
                                                float* __restrict__ C, int ldc, int cSz,
                                                int K, float alpha) {
    __shared__ float As[32][18];
    __shared__ float Bs[32][34];
    int t = threadIdx.x;
    const float* Ab = A + (size_t)blockIdx.z * aSz + (size_t)(blockIdx.x * 16) * lda;
    const float* Bb = TRANSB ? (B + (size_t)blockIdx.z * bSz + (size_t)(blockIdx.y * 32) * ldb)
                             : (B + (size_t)blockIdx.z * bSz + blockIdx.y * 32);
    float* Cb = C + (size_t)blockIdx.z * cSz + (size_t)(blockIdx.x * 16) * ldc + blockIdx.y * 32;
    int ty = t >> 4, tx = t & 15;
    int r = t >> 3, q = (t & 7) * 4;
    float a00 = 0.f, a01 = 0.f, a10 = 0.f, a11 = 0.f;

    float4 av, bv0, bv1;
    av = *(const float4*)(Ab + (size_t)r * lda + q);
    bv0 = *(const float4*)(Bb + (size_t)r * ldb + q);
    bv1 = *(const float4*)(Bb + (size_t)(r + 16) * ldb + q);
    int nk = K / 32;
    for (int kt = 0; kt < nk; kt++) {
        As[q + 0][r] = av.x; As[q + 1][r] = av.y; As[q + 2][r] = av.z; As[q + 3][r] = av.w;
        if (TRANSB) {
            Bs[q + 0][r] = bv0.x; Bs[q + 1][r] = bv0.y; Bs[q + 2][r] = bv0.z; Bs[q + 3][r] = bv0.w;
            Bs[q + 0][r + 16] = bv1.x; Bs[q + 1][r + 16] = bv1.y; Bs[q + 2][r + 16] = bv1.z; Bs[q + 3][r + 16] = bv1.w;
        } else {
            Bs[r][q + 0] = bv0.x; Bs[r][q + 1] = bv0.y; Bs[r][q + 2] = bv0.z; Bs[r][q + 3] = bv0.w;
            Bs[r + 16][q + 0] = bv1.x; Bs[r + 16][q + 1] = bv1.y; Bs[r + 16][q + 2] = bv1.z; Bs[r + 16][q + 3] = bv1.w;
        }
        __syncthreads();
        if (kt + 1 < nk) {
            int k0 = (kt + 1) * 32;
            av = *(const float4*)(Ab + (size_t)r * lda + k0 + q);
            if (TRANSB) {
                bv0 = *(const float4*)(Bb + (size_t)r * ldb + k0 + q);
                bv1 = *(const float4*)(Bb + (size_t)(r + 16) * ldb + k0 + q);
            } else {
                bv0 = *(const float4*)(Bb + (size_t)(k0 + r) * ldb + q);
                bv1 = *(const float4*)(Bb + (size_t)(k0 + r + 16) * ldb + q);
            }
        }
        #pragma unroll
        for (int k = 0; k < 32; k++) {
            float2 a = *(const float2*)&As[k][ty * 2];
            float2 b = *(const float2*)&Bs[k][tx * 2];
            a00 = fmaf(a.x, b.x, a00); a01 = fmaf(a.x, b.y, a01);
            a10 = fmaf(a.y, b.x, a10); a11 = fmaf(a.y, b.y, a11);
        }
        __syncthreads();
    }
    Cb[(size_t)(ty * 2) * ldc + tx * 2]     = alpha * a00;
    Cb[(size_t)(ty * 2) * ldc + tx * 2 + 1] = alpha * a01;
    Cb[(size_t)(ty * 2 + 1) * ldc + tx * 2]     = alpha * a10;
    Cb[(size_t)(ty * 2 + 1) * ldc + tx * 2 + 1] = alpha * a11;
}

// ---------------- Fused q1+qk: grid (16 b-tiles, 8 heads), 128 threads ----------------
__global__ void __launch_bounds__(128) k_q1qk(const float* __restrict__ Wq1,
                                              const float* __restrict__ Wk1) {
    __shared__ float As[32][18];
    __shared__ float Bs[32][34];
    __shared__ __align__(16) float q1s[16][36];
    int t = threadIdx.x;
    int bx = blockIdx.x, h = blockIdx.y;
    const int LDA = 3 * Dc;
    const float* Ab = g_ctx + (size_t)(bx * 16) * LDA;
    const float* Bb = Wq1 + h * 32;
    int ty = t >> 4, tx = t & 15;
    int r = t >> 3, q = (t & 7) * 4;
    float a00 = 0.f, a01 = 0.f, a10 = 0.f, a11 = 0.f;

    float4 av  = *(const float4*)(Ab + (size_t)r * LDA + q);
    float4 bv0 = *(const float4*)(Bb + (size_t)r * Dc + q);
    float4 bv1 = *(const float4*)(Bb + (size_t)(r + 16) * Dc + q);
    const int nk = LDA / 32;
    for (int kt = 0; kt < nk; kt++) {
        As[q + 0][r] = av.x; As[q + 1][r] = av.y; As[q + 2][r] = av.z; As[q + 3][r] = av.w;
        Bs[r][q + 0] = bv0.x; Bs[r][q + 1] = bv0.y; Bs[r][q + 2] = bv0.z; Bs[r][q + 3] = bv0.w;
        Bs[r + 16][q + 0] = bv1.x; Bs[r + 16][q + 1] = bv1.y; Bs[r + 16][q + 2] = bv1.z; Bs[r + 16][q + 3] = bv1.w;
        __syncthreads();
        if (kt + 1 < nk) {
            int k0 = (kt + 1) * 32;
            av  = *(const float4*)(Ab + (size_t)r * LDA + k0 + q);
            bv0 = *(const float4*)(Bb + (size_t)(k0 + r) * Dc + q);
            bv1 = *(const float4*)(Bb + (size_t)(k0 + r + 16) * Dc + q);
        }
        #pragma unroll
        for (int k = 0; k < 32; k++) {
            float2 a = *(const float2*)&As[k][ty * 2];
            float2 b = *(const float2*)&Bs[k][tx * 2];
            a00 = fmaf(a.x, b.x, a00); a01 = fmaf(a.x, b.y, a01);
            a10 = fmaf(a.y, b.x, a10); a11 = fmaf(a.y, b.y, a11);
        }
        __syncthreads();
    }
    q1s[ty * 2][tx * 2]     = a00;
    q1s[ty * 2][tx * 2 + 1] = a01;
    q1s[ty * 2 + 1][tx * 2]     = a10;
    q1s[ty * 2 + 1][tx * 2 + 1] = a11;
    __syncthreads();

    int bhalf = t >> 6, ig = t & 63;
    const float* wbase = Wk1 + (size_t)(ig * 4) * Dc + h * 32;
    #pragma unroll 2
    for (int bb = 0; bb < 8; bb++) {
        int bloc = bhalf * 8 + bb;
        float s0 = 0.f, s1 = 0.f, s2 = 0.f, s3 = 0.f;
        #pragma unroll
        for (int dq = 0; dq < 8; dq++) {
            float4 qv = *(const float4*)&q1s[bloc][dq * 4];
            float4 w0 = *(const float4*)(wbase + 0 * Dc + dq * 4);
            float4 w1 = *(const float4*)(wbase + 1 * Dc + dq * 4);
            float4 w2 = *(const float4*)(wbase + 2 * Dc + dq * 4);
            float4 w3 = *(const float4*)(wbase + 3 * Dc + dq * 4);
            s0 += qv.x * w0.x + qv.y * w0.y + qv.z * w0.z + qv.w * w0.w;
            s1 += qv.x * w1.x + qv.y * w1.y + qv.z * w1.z + qv.w * w1.w;
            s2 += qv.x * w2.x + qv.y * w2.y + qv.z * w2.z + qv.w * w2.w;
            s3 += qv.x * w3.x + qv.y * w3.y + qv.z * w3.z + qv.w * w3.w;
        }
        const float sc = 0.17677669529663687f;
        float4 o = make_float4(s0 * sc, s1 * sc, s2 * sc, s3 * sc);
        *(float4*)&g_qk[(((size_t)(bx * 16 + bloc)) * Hc + h) * Dc + ig * 4] = o;
    }
}

// ---------------- Pass 1: partial sums for hbar. grid (64, MEAN_CH), block 256 ----------------
__global__ void k_mean_part(const float* __restrict__ ebp) {
    int cg = blockIdx.x * 256 + threadIdx.x;
    int l0 = blockIdx.y * (Lc / MEAN_CH);
    const float4* p = (const float4*)ebp + (size_t)l0 * (Bc * Dc / 4) + cg;
    float4 a0 = {0,0,0,0}, a1 = {0,0,0,0}, a2 = {0,0,0,0}, a3 = {0,0,0,0};
    #pragma unroll 2
    for (int l = 0; l < Lc / MEAN_CH; l += 8) {
        float4 v0 = p[(size_t)(l + 0) * (Bc * Dc / 4)];
        float4 v1 = p[(size_t)(l + 1) * (Bc * Dc / 4)];
        float4 v2 = p[(size_t)(l + 2) * (Bc * Dc / 4)];
        float4 v3 = p[(size_t)(l + 3) * (Bc * Dc / 4)];
        float4 v4 = p[(size_t)(l + 4) * (Bc * Dc / 4)];
        float4 v5 = p[(size_t)(l + 5) * (Bc * Dc / 4)];
        float4 v6 = p[(size_t)(l + 6) * (Bc * Dc / 4)];
        float4 v7 = p[(size_t)(l + 7) * (Bc * Dc / 4)];
        a0.x += v0.x; a0.y += v0.y; a0.z += v0.z; a0.w += v0.w;
        a1.x += v1.x; a1.y += v1.y; a1.z += v1.z; a1.w += v1.w;
        a2.x += v2.x; a2.y += v2.y; a2.z += v2.z; a2.w += v2.w;
        a3.x += v3.x; a3.y += v3.y; a3.z += v3.z; a3.w += v3.w;
        a0.x += v4.x; a0.y += v4.y; a0.z += v4.z; a0.w += v4.w;
        a1.x += v5.x; a1.y += v5.y; a1.z += v5.z; a1.w += v5.w;
        a2.x += v6.x; a2.y += v6.y; a2.z += v6.z; a2.w += v6.w;
        a3.x += v7.x; a3.y += v7.y; a3.z += v7.z; a3.w += v7.w;
    }
    float4 r;
    r.x = (a0.x + a1.x) + (a2.x + a3.x);
    r.y = (a0.y + a1.y) + (a2.y + a3.y);
    r.z = (a0.z + a1.z) + (a2.z + a3.z);
    r.w = (a0.w + a1.w) + (a2.w + a3.w);
    ((float4*)g_hbar_part[blockIdx.y])[cg] = r;
}

// ---------------- ctx assembly: grid (Bc, 3). seg 0: hbar; seg 1: prev; seg 2: first ------------
__global__ void k_ctx(const float* __restrict__ ebp, const int* __restrict__ pa) {
    int b = blockIdx.x, seg = blockIdx.y, t = threadIdx.x;
    if (seg == 0) {
        float hs = 0.f;
        #pragma unroll
        for (int c = 0; c < MEAN_CH; c++) hs += g_hbar_part[c][b * Dc + t];
        g_ctx[b * 3 * Dc + t] = hs * (1.0f / Lc);
    } else if (seg == 1) {
        int aL = pa[b * Tc + (Tc - 1)];
        g_ctx[b * 3 * Dc + Dc + t] = ebp[((size_t)aL * Bc + b) * Dc + t];
    } else {
        int a0 = pa[b * Tc];
        g_ctx[b * 3 * Dc + 2 * Dc + t] = ebp[((size_t)a0 * Bc + b) * Dc + t];
    }
}

// ---------------- Fused flash pass: 4x16-row cp.async quarters (R14 verbatim) ----------------
__global__ void __launch_bounds__(256, 2) k_flash(const float* __restrict__ ebp,
                                                  const int* __restrict__ pa) {
    extern __shared__ float smem[];
    float* tile = smem;                       // [64][256]
    float* wsc  = smem + 64 * 256;            // [64][8]
    unsigned* mb = (unsigned*)(wsc + 64 * 8);
    int b = blockIdx.x, cy = blockIdx.y, t = threadIdx.x;
    int warp = t >> 5, lane = t & 31;
    int l0 = cy * 64;

    if (t < 32) mb[t] = 0u;
    int lr = t >> 4, lp = (t & 15) * 16;
    #pragma unroll
    for (int qd = 0; qd < 4; qd++) {
        const float* src = ebp + ((size_t)(l0 + qd * 16 + lr) * Bc + b) * Dc + lp;
        unsigned int sa = (unsigned int)__cvta_generic_to_shared(tile + (qd * 16 + lr) * 256 + lp);
        #pragma unroll
        for (int k = 0; k < 4; k++) cp_async16(sa + k * 16, src + k * 4);
        asm volatile("cp.async.commit_group;");
    }
    __syncthreads();
    if (t < Tc) {
        int a = pa[b * Tc + t];
        atomicOr(&mb[a >> 5], 1u << (a & 31));
    }

    unsigned long long qkp[Hc][4];
    {
        const ulonglong2* qb = (const ulonglong2*)(g_qk + b * Hc * Dc);
        #pragma unroll
        for (int h = 0; h < Hc; h++) {
            ulonglong2 u0 = qb[h * (Dc / 4) + lane * 2];
            ulonglong2 u1 = qb[h * (Dc / 4) + lane * 2 + 1];
            qkp[h][0] = u0.x; qkp[h][1] = u0.y; qkp[h][2] = u1.x; qkp[h][3] = u1.y;
        }
    }

    #pragma unroll
    for (int qd = 0; qd < 4; qd++) {
        if (qd == 0)      asm volatile("cp.async.wait_group 3;" ::: "memory");
        else if (qd == 1) asm volatile("cp.async.wait_group 2;" ::: "memory");
        else if (qd == 2) asm volatile("cp.async.wait_group 1;" ::: "memory");
        else              asm volatile("cp.async.wait_group 0;" ::: "memory");
        __syncthreads();
        #pragma unroll
        for (int j = 0; j < 2; j++) {
            int r = qd * 16 + warp * 2 + j;
            const ulonglong2* rp = (const ulonglong2*)(tile + r * 256) + lane * 2;
            ulonglong2 A = rp[0], B = rp[1];
            unsigned long long e[4] = {A.x, A.y, B.x, B.y};
            float sc[Hc];
            #pragma unroll
            for (int h = 0; h < Hc; h++) {
                unsigned long long acc = 0ull;
                #pragma unroll
                for (int q = 0; q < 4; q++) fma2(acc, e[q], qkp[h][q]);
                float2 f = ull2f2(acc);
                sc[h] = f.x + f.y;
            }
            float v = fold8(sc, lane);
            if ((lane & 3) == 0) {
                int h = lane >> 2;
                int l = l0 + r;
                bool m = (mb[l >> 5] >> (l & 31)) & 1u;
                wsc[r * 8 + h] = m ? -1e4f : v;
            }
        }
    }
    __syncthreads();

    {
        int h = warp;
        float lv0 = wsc[lane * 8 + h];
        float lv1 = wsc[(lane + 32) * 8 + h];
        float m = fmaxf(lv0, lv1);
        #pragma unroll
        for (int o = 16; o > 0; o >>= 1) m = fmaxf(m, __shfl_xor_sync(0xffffffffu, m, o));
        float w0 = __expf(lv0 - m), w1 = __expf(lv1 - m);
        float s = w0 + w1;
        #pragma unroll
        for (int o = 16; o > 0; o >>= 1) s += __shfl_xor_sync(0xffffffffu, s, o);
        wsc[lane * 8 + h] = w0;
        wsc[(lane + 32) * 8 + h] = w1;
        if (lane == 0) g_ms[(b * FL_CH + cy) * Hc + h] = make_float2(m, s);
    }
    __syncthreads();

    unsigned long long acc[4] = {0ull, 0ull, 0ull, 0ull};
    const ulonglong2* wrow = (const ulonglong2*)wsc;
    #pragma unroll 8
    for (int r = 0; r < 64; r++) {
        ulonglong2 w01 = wrow[r * 2];
        ulonglong2 w23 = wrow[r * 2 + 1];
        float e = tile[r * 256 + t];
        unsigned long long ee = f2ull(e, e);
        fma2(acc[0], w01.x, ee);
        fma2(acc[1], w01.y, ee);
        fma2(acc[2], w23.x, ee);
        fma2(acc[3], w23.y, ee);
    }
    #pragma unroll
    for (int hp = 0; hp < 4; hp++) {
        float2 f2v = ull2f2(acc[hp]);
        g_wE_part[cy][(b * Hc + 2 * hp) * Dc + t]     = f2v.x;
        g_wE_part[cy][(b * Hc + 2 * hp + 1) * Dc + t] = f2v.y;
    }
}

// ---------------- Fused combine + head_out GEMM. grid (16 b-tiles, 8 heads), 256 thr ----------
// Stage 1: wEs[bl][i] = sum_c wE_part[c][(b,h),i] * cf[b][c]   (exact softmax combine)
// Stage 2: ho[b, h*32+d] = sum_i wEs[bl][i] * Wv1[i, h*32+d]
__global__ void __launch_bounds__(256) k_combho(const float* __restrict__ Wv1) {
    __shared__ float wEs[16][260];    // padded rows
    __shared__ float cfs[16][FL_CH];
    int t = threadIdx.x;
    int bx = blockIdx.x, h = blockIdx.y;
    if (t < 16) {
        int b = bx * 16 + t;
        float2 ms[FL_CH];
        float M = -1e30f;
        #pragma unroll
        for (int c = 0; c < FL_CH; c++) {
            ms[c] = g_ms[(b * FL_CH + c) * Hc + h];
            M = fmaxf(M, ms[c].x);
        }
        float S = 0.f;
        float ef[FL_CH];
        #pragma unroll
        for (int c = 0; c < FL_CH; c++) {
            ef[c] = __expf(ms[c].x - M);
            S += ms[c].y * ef[c];
        }
        float invS = 1.0f / S;
        #pragma unroll
        for (int c = 0; c < FL_CH; c++) cfs[t][c] = ef[c] * invS;
    }
    __syncthreads();
    // combine: thread t owns column i=t; loop over 16 local b's
    #pragma unroll 4
    for (int bl = 0; bl < 16; bl++) {
        int bh = (bx * 16 + bl) * Hc + h;
        float s = 0.f;
        #pragma unroll
        for (int c = 0; c < FL_CH; c++)
            s += g_wE_part[c][(size_t)bh * Dc + t] * cfs[bl][c];
        wEs[bl][t] = s;
    }
    __syncthreads();
    // head_out: thread = (blh = t>>5 in 0..7, d = t&31); handles bl = blh and blh+8
    int d = t & 31, blh = t >> 5;
    float s0 = 0.f, s1 = 0.f;
    const float* wv = Wv1 + h * 32 + d;
    #pragma unroll 8
    for (int i = 0; i < Dc; i++) {
        float w = wv[(size_t)i * Dc];
        s0 = fmaf(wEs[blh][i], w, s0);
        s1 = fmaf(wEs[blh + 8][i], w, s1);
    }
    g_ho[(size_t)(bx * 16 + blh) * Dc + h * 32 + d]     = s0;
    g_ho[(size_t)(bx * 16 + blh + 8) * Dc + h * 32 + d] = s1;
}

// ---------------- Pass 4a: fs. grid (Bc, 4), register prefetch, fold4 ----------
__global__ void __launch_bounds__(256, 2) k_fs(const float* __restrict__ ebp,
                                               const int* __restrict__ pa) {
    int b = blockIdx.x, t = threadIdx.x;
    int warp = t >> 5, lane = t & 31;
    int l0 = blockIdx.y * 256;
    __shared__ unsigned mbits[32];
    if (t < 32) mbits[t] = 0u;
    __syncthreads();
    if (t < Tc) {
        int a = pa[b * Tc + t];
        atomicOr(&mbits[a >> 5], 1u << (a & 31));
    }
    __syncthreads();
    unsigned long long qp[4];
    {
        const ulonglong2* qb = (const ulonglong2*)(g_qk2 + b * Dc);
        ulonglong2 u0 = qb[lane * 2], u1 = qb[lane * 2 + 1];
        qp[0] = u0.x; qp[1] = u0.y; qp[2] = u1.x; qp[3] = u1.y;
    }
    int base = l0 + warp;
    ulonglong2 cur[4][2], nxt[4][2];
    #pragma unroll
    for (int i = 0; i < 4; i++) {
        const ulonglong2* p = (const ulonglong2*)(ebp + ((size_t)(base + i * 8) * Bc + b) * Dc) + lane * 2;
        cur[i][0] = p[0]; cur[i][1] = p[1];
    }
    #pragma unroll 2
    for (int g = 0; g < 8; g++) {
        if (g < 7) {
            #pragma unroll
            for (int i = 0; i < 4; i++) {
                const ulonglong2* p = (const ulonglong2*)(ebp + ((size_t)(base + ((g + 1) * 4 + i) * 8) * Bc + b) * Dc) + lane * 2;
                nxt[i][0] = p[0]; nxt[i][1] = p[1];
            }
        }
        float r[4];
        #pragma unroll
        for (int i = 0; i < 4; i++) {
            unsigned long long acc = 0ull;
            fma2(acc, cur[i][0].x, qp[0]);
            fma2(acc, cur[i][0].y, qp[1]);
            fma2(acc, cur[i][1].x, qp[2]);
            fma2(acc, cur[i][1].y, qp[3]);
            float2 f = ull2f2(acc);
            r[i] = f.x + f.y;
        }
        float v = fold4(r, lane);
        if ((lane & 7) == 0) {
            int l = base + (g * 4 + (lane >> 3)) * 8;
            bool m = (mbits[l >> 5] >> (l & 31)) & 1u;
            g_fs[b * Lc + l] = m ? -1e30f : tanhf(v) * 10.0f;
        }
        #pragma unroll
        for (int i = 0; i < 4; i++) { cur[i][0] = nxt[i][0]; cur[i][1] = nxt[i][1]; }
    }
}

// ---------------- Pass 4b: per-b softmax over l ----------------
__global__ void k_out(float* __restrict__ out) {
    int b = blockIdx.x, t = threadIdx.x;
    int warp = t >> 5, lane = t & 31;
    __shared__ float red[32];
    float v = g_fs[b * Lc + t];
    float e = __expf(v - 10.0f);
    float sm = e;
    #pragma unroll
    for (int o = 16; o > 0; o >>= 1) sm += __shfl_xor_sync(0xffffffffu, sm, o);
    if (lane == 0) red[warp] = sm;
    __syncthreads();
    if (t < 32) {
        float s = red[t];
        #pragma unroll
        for (int o = 16; o > 0; o >>= 1) s += __shfl_xor_sync(0xffffffffu, s, o);
        red[t] = s;
    }
    __syncthreads();
    out[(size_t)t * Bc + b] = e * (1.0f / red[0]);
}

extern "C" void kernel_launch(void* const* d_in, const int* in_sizes, int n_in,
                              void* d_out, int out_size) {
    const float* ebp = (const float*)d_in[0];
    const int*   pa  = (const int*)d_in[1];
    const float* Wq1 = (const float*)d_in[2];
    const float* Wk1 = (const float*)d_in[3];
    const float* Wv1 = (const float*)d_in[4];
    const float* Wo1 = (const float*)d_in[5];
    const float* Wq2 = (const float*)d_in[6];
    const float* Wk2 = (const float*)d_in[7];
    float* out = (float*)d_out;

    static int init_done = 0;
    static cudaStream_t s2 = nullptr;
    static cudaEvent_t evStart = nullptr, evW = nullptr;
    const int FLASH_SMEM = 64 * 256 * 4 + 64 * 8 * 4 + 128;  // 67712
    if (!init_done) {
        cudaFuncSetAttribute(k_flash, cudaFuncAttributeMaxDynamicSharedMemorySize, FLASH_SMEM);
        cudaStreamCreate(&s2);
        cudaEventCreateWithFlags(&evStart, cudaEventDisableTiming);
        cudaEventCreateWithFlags(&evW, cudaEventDisableTiming);
        init_done = 1;
    }

    float* d_Wt1;    cudaGetSymbolAddress((void**)&d_Wt1,    g_Wt1);
    float* d_Wcombo; cudaGetSymbolAddress((void**)&d_Wcombo, g_Wcombo);
    float* d_ho;     cudaGetSymbolAddress((void**)&d_ho,     g_ho);
    float* d_qk2;    cudaGetSymbolAddress((void**)&d_qk2,    g_qk2);

    // ---- fork side stream: precompute Wcombo = (Wo1 @ Wq2 @ Wk2^T)/16 ----
    cudaEventRecord(evStart, 0);
    cudaStreamWaitEvent(s2, evStart, 0);
    k_gemm16<0><<<dim3(16, 8, 1), 128, 0, s2>>>(Wo1, Dc, 0, Wq2, Dc, 0,
                                                d_Wt1, Dc, 0, Dc, 1.0f);
    k_gemm16<1><<<dim3(16, 8, 1), 128, 0, s2>>>(d_Wt1, Dc, 0, Wk2, Dc, 0,
                                                d_Wcombo, Dc, 0, Dc, 1.0f / 16.0f);
    cudaEventRecord(evW, s2);

    // ---- main stream ----
    dim3 gm(64, MEAN_CH);
    k_mean_part<<<gm, 256>>>(ebp);
    k_ctx<<<dim3(Bc, 3), 256>>>(ebp, pa);
    k_q1qk<<<dim3(16, 8), 128>>>(Wq1, Wk1);

    dim3 gf(Bc, FL_CH);
    k_flash<<<gf, 256, FLASH_SMEM>>>(ebp, pa);
    k_combho<<<dim3(16, Hc), 256>>>(Wv1);

    // join side stream, then qk2 = ho @ Wcombo
    cudaStreamWaitEvent(0, evW, 0);
    k_gemm16<0><<<dim3(16, 8, 1), 128>>>(d_ho, Dc, 0, d_Wcombo, Dc, 0,
                                         d_qk2, Dc, 0, Dc, 1.0f);

    dim3 gs(Bc, 4);
    k_fs<<<gs, 256>>>(ebp, pa);
    k_out<<<Bc, 1024>>>(out);
}

// round 16
// speedup vs baseline: 1.0764x; 1.0764x over previous
#include <cuda_runtime.h>

#define Lc 1024
#define Bc 256
#define Dc 256
#define Tc 50
#define Hc 8
#define DHc 32

#define MEAN_CH 16  // L-chunks for mean pass
#define FL_CH 16    // L-chunks for flash pass (64 rows each)

// Scratch (allocation-free rule: __device__ globals)
__device__ float g_hbar_part[MEAN_CH][Bc*Dc];
__device__ float g_ctx[Bc*3*Dc];                // [b][0..767]
__device__ float g_qk[Bc*Hc*Dc];                // [b][h][i], includes 1/sqrt(32)
__device__ float g_wE_part[FL_CH][Bc*Hc*Dc];    // unnormalized partial [b][h][i]
__device__ float2 g_ms[Bc*FL_CH*Hc];            // (m, s) per (b, chunk, h)
__device__ float g_wEn[Bc*Hc*Dc];               // normalized wE
__device__ float g_ho[Bc*Dc];                   // head_out flattened
__device__ float g_qk2[Bc*Dc];                  // includes 1/16
__device__ float g_fs[Bc*Lc];                   // [b][l]
__device__ float g_Wt1[Dc*Dc];                  // Wo1 @ Wq2
__device__ float g_Wcombo[Dc*Dc];               // (Wo1 @ Wq2 @ Wk2^T) / 16

__device__ __forceinline__ unsigned long long f2ull(float x, float y) {
    unsigned long long u;
    asm("mov.b64 %0, {%1,%2};" : "=l"(u) : "f"(x), "f"(y));
    return u;
}
__device__ __forceinline__ float2 ull2f2(unsigned long long u) {
    float2 f;
    asm("mov.b64 {%0,%1}, %2;" : "=f"(f.x), "=f"(f.y) : "l"(u));
    return f;
}
__device__ __forceinline__ void fma2(unsigned long long& acc, unsigned long long a, unsigned long long b) {
    asm("fma.rn.f32x2 %0, %1, %2, %3;" : "=l"(acc) : "l"(a), "l"(b), "l"(acc));
}
__device__ __forceinline__ void cp_async16(unsigned int saddr, const void* g) {
    asm volatile("cp.async.cg.shared.global [%0], [%1], 16;" :: "r"(saddr), "l"(g));
}

// 8-value fold reduction: lanes with lane%4==0 hold full sum for head (lane>>2). 9 shuffles.
__device__ __forceinline__ float fold8(const float sc[8], int lane) {
    bool hi16 = (lane & 16) != 0;
    float n[4];
    #pragma unroll
    for (int k = 0; k < 4; k++) {
        float give = hi16 ? sc[k] : sc[4 + k];
        float keep = hi16 ? sc[4 + k] : sc[k];
        n[k] = keep + __shfl_xor_sync(0xffffffffu, give, 16);
    }
    bool hi8 = (lane & 8) != 0;
    float m[2];
    #pragma unroll
    for (int j = 0; j < 2; j++) {
        float give = hi8 ? n[j] : n[2 + j];
        float keep = hi8 ? n[2 + j] : n[j];
        m[j] = keep + __shfl_xor_sync(0xffffffffu, give, 8);
    }
    bool hi4 = (lane & 4) != 0;
    float give = hi4 ? m[0] : m[1];
    float keep = hi4 ? m[1] : m[0];
    float v = keep + __shfl_xor_sync(0xffffffffu, give, 4);
    v += __shfl_xor_sync(0xffffffffu, v, 1);
    v += __shfl_xor_sync(0xffffffffu, v, 2);
    return v;
}

// 4-value fold: lanes with lane%8==0 hold row (lane>>3).
__device__ __forceinline__ float fold4(const float r[4], int lane) {
    bool hi16 = (lane & 16) != 0;
    float n[2];
    #pragma unroll
    for (int j = 0; j < 2; j++) {
        float give = hi16 ? r[j] : r[2 + j];
        float keep = hi16 ? r[2 + j] : r[j];
        n[j] = keep + __shfl_xor_sync(0xffffffffu, give, 16);
    }
    bool hi8 = (lane & 8) != 0;
    float give = hi8 ? n[0] : n[1];
    float keep = hi8 ? n[1] : n[0];
    float v = keep + __shfl_xor_sync(0xffffffffu, give, 8);
    v += __shfl_xor_sync(0xffffffffu, v, 4);
    v += __shfl_xor_sync(0xffffffffu, v, 2);
    v += __shfl_xor_sync(0xffffffffu, v, 1);
    return v;
}

// ---------------- 16x32-tile GEMM with register-prefetched K-tiles, 128 threads ----------------
template<int TRANSB>
__global__ void __launch_bounds__(128) k_gemm16(const float* __restrict__ A, int lda, int aSz,
                                                const float* __restrict__ B, int ldb, int bSz,
                                                float* __restrict__ C, int ldc, int cSz,
                                                int K, float alpha) {
    __shared__ float As[32][18];
    __shared__ float Bs[32][34];
    int t = threadIdx.x;
    const float* Ab = A + (size_t)blockIdx.z * aSz + (size_t)(blockIdx.x * 16) * lda;
    const float* Bb = TRANSB ? (B + (size_t)blockIdx.z * bSz + (size_t)(blockIdx.y * 32) * ldb)
                             : (B + (size_t)blockIdx.z * bSz + blockIdx.y * 32);
    float* Cb = C + (size_t)blockIdx.z * cSz + (size_t)(blockIdx.x * 16) * ldc + blockIdx.y * 32;
    int ty = t >> 4, tx = t & 15;
    int r = t >> 3, q = (t & 7) * 4;
    float a00 = 0.f, a01 = 0.f, a10 = 0.f, a11 = 0.f;

    float4 av, bv0, bv1;
    av = *(const float4*)(Ab + (size_t)r * lda + q);
    bv0 = *(const float4*)(Bb + (size_t)r * ldb + q);
    bv1 = *(const float4*)(Bb + (size_t)(r + 16) * ldb + q);
    int nk = K / 32;
    for (int kt = 0; kt < nk; kt++) {
        As[q + 0][r] = av.x; As[q + 1][r] = av.y; As[q + 2][r] = av.z; As[q + 3][r] = av.w;
        if (TRANSB) {
            Bs[q + 0][r] = bv0.x; Bs[q + 1][r] = bv0.y; Bs[q + 2][r] = bv0.z; Bs[q + 3][r] = bv0.w;
            Bs[q + 0][r + 16] = bv1.x; Bs[q + 1][r + 16] = bv1.y; Bs[q + 2][r + 16] = bv1.z; Bs[q + 3][r + 16] = bv1.w;
        } else {
            Bs[r][q + 0] = bv0.x; Bs[r][q + 1] = bv0.y; Bs[r][q + 2] = bv0.z; Bs[r][q + 3] = bv0.w;
            Bs[r + 16][q + 0] = bv1.x; Bs[r + 16][q + 1] = bv1.y; Bs[r + 16][q + 2] = bv1.z; Bs[r + 16][q + 3] = bv1.w;
        }
        __syncthreads();
        if (kt + 1 < nk) {
            int k0 = (kt + 1) * 32;
            av = *(const float4*)(Ab + (size_t)r * lda + k0 + q);
            if (TRANSB) {
                bv0 = *(const float4*)(Bb + (size_t)r * ldb + k0 + q);
                bv1 = *(const float4*)(Bb + (size_t)(r + 16) * ldb + k0 + q);
            } else {
                bv0 = *(const float4*)(Bb + (size_t)(k0 + r) * ldb + q);
                bv1 = *(const float4*)(Bb + (size_t)(k0 + r + 16) * ldb + q);
            }
        }
        #pragma unroll
        for (int k = 0; k < 32; k++) {
            float2 a = *(const float2*)&As[k][ty * 2];
            float2 b = *(const float2*)&Bs[k][tx * 2];
            a00 = fmaf(a.x, b.x, a00); a01 = fmaf(a.x, b.y, a01);
            a10 = fmaf(a.y, b.x, a10); a11 = fmaf(a.y, b.y, a11);
        }
        __syncthreads();
    }
    Cb[(size_t)(ty * 2) * ldc + tx * 2]     = alpha * a00;
    Cb[(size_t)(ty * 2) * ldc + tx * 2 + 1] = alpha * a01;
    Cb[(size_t)(ty * 2 + 1) * ldc + tx * 2]     = alpha * a10;
    Cb[(size_t)(ty * 2 + 1) * ldc + tx * 2 + 1] = alpha * a11;
}

// ---------------- Fused q1+qk: grid (16 b-tiles, 8 heads), 128 threads ----------------
__global__ void __launch_bounds__(128) k_q1qk(const float* __restrict__ Wq1,
                                              const float* __restrict__ Wk1) {
    __shared__ float As[32][18];
    __shared__ float Bs[32][34];
    __shared__ __align__(16) float q1s[16][36];
    int t = threadIdx.x;
    int bx = blockIdx.x, h = blockIdx.y;
    const int LDA = 3 * Dc;
    const float* Ab = g_ctx + (size_t)(bx * 16) * LDA;
    const float* Bb = Wq1 + h * 32;
    int ty = t >> 4, tx = t & 15;
    int r = t >> 3, q = (t & 7) * 4;
    float a00 = 0.f, a01 = 0.f, a10 = 0.f, a11 = 0.f;

    float4 av  = *(const float4*)(Ab + (size_t)r * LDA + q);
    float4 bv0 = *(const float4*)(Bb + (size_t)r * Dc + q);
    float4 bv1 = *(const float4*)(Bb + (size_t)(r + 16) * Dc + q);
    const int nk = LDA / 32;
    for (int kt = 0; kt < nk; kt++) {
        As[q + 0][r] = av.x; As[q + 1][r] = av.y; As[q + 2][r] = av.z; As[q + 3][r] = av.w;
        Bs[r][q + 0] = bv0.x; Bs[r][q + 1] = bv0.y; Bs[r][q + 2] = bv0.z; Bs[r][q + 3] = bv0.w;
        Bs[r + 16][q + 0] = bv1.x; Bs[r + 16][q + 1] = bv1.y; Bs[r + 16][q + 2] = bv1.z; Bs[r + 16][q + 3] = bv1.w;
        __syncthreads();
        if (kt + 1 < nk) {
            int k0 = (kt + 1) * 32;
            av  = *(const float4*)(Ab + (size_t)r * LDA + k0 + q);
            bv0 = *(const float4*)(Bb + (size_t)(k0 + r) * Dc + q);
            bv1 = *(const float4*)(Bb + (size_t)(k0 + r + 16) * Dc + q);
        }
        #pragma unroll
        for (int k = 0; k < 32; k++) {
            float2 a = *(const float2*)&As[k][ty * 2];
            float2 b = *(const float2*)&Bs[k][tx * 2];
            a00 = fmaf(a.x, b.x, a00); a01 = fmaf(a.x, b.y, a01);
            a10 = fmaf(a.y, b.x, a10); a11 = fmaf(a.y, b.y, a11);
        }
        __syncthreads();
    }
    q1s[ty * 2][tx * 2]     = a00;
    q1s[ty * 2][tx * 2 + 1] = a01;
    q1s[ty * 2 + 1][tx * 2]     = a10;
    q1s[ty * 2 + 1][tx * 2 + 1] = a11;
    __syncthreads();

    int bhalf = t >> 6, ig = t & 63;
    const float* wbase = Wk1 + (size_t)(ig * 4) * Dc + h * 32;
    #pragma unroll 2
    for (int bb = 0; bb < 8; bb++) {
        int bloc = bhalf * 8 + bb;
        float s0 = 0.f, s1 = 0.f, s2 = 0.f, s3 = 0.f;
        #pragma unroll
        for (int dq = 0; dq < 8; dq++) {
            float4 qv = *(const float4*)&q1s[bloc][dq * 4];
            float4 w0 = *(const float4*)(wbase + 0 * Dc + dq * 4);
            float4 w1 = *(const float4*)(wbase + 1 * Dc + dq * 4);
            float4 w2 = *(const float4*)(wbase + 2 * Dc + dq * 4);
            float4 w3 = *(const float4*)(wbase + 3 * Dc + dq * 4);
            s0 += qv.x * w0.x + qv.y * w0.y + qv.z * w0.z + qv.w * w0.w;
            s1 += qv.x * w1.x + qv.y * w1.y + qv.z * w1.z + qv.w * w1.w;
            s2 += qv.x * w2.x + qv.y * w2.y + qv.z * w2.z + qv.w * w2.w;
            s3 += qv.x * w3.x + qv.y * w3.y + qv.z * w3.z + qv.w * w3.w;
        }
        const float sc = 0.17677669529663687f;
        float4 o = make_float4(s0 * sc, s1 * sc, s2 * sc, s3 * sc);
        *(float4*)&g_qk[(((size_t)(bx * 16 + bloc)) * Hc + h) * Dc + ig * 4] = o;
    }
}

// ---------------- Pass 1: partial sums for hbar. grid (64, MEAN_CH), block 256 ----------------
__global__ void k_mean_part(const float* __restrict__ ebp) {
    int cg = blockIdx.x * 256 + threadIdx.x;
    int l0 = blockIdx.y * (Lc / MEAN_CH);
    const float4* p = (const float4*)ebp + (size_t)l0 * (Bc * Dc / 4) + cg;
    float4 a0 = {0,0,0,0}, a1 = {0,0,0,0}, a2 = {0,0,0,0}, a3 = {0,0,0,0};
    #pragma unroll 2
    for (int l = 0; l < Lc / MEAN_CH; l += 8) {
        float4 v0 = p[(size_t)(l + 0) * (Bc * Dc / 4)];
        float4 v1 = p[(size_t)(l + 1) * (Bc * Dc / 4)];
        float4 v2 = p[(size_t)(l + 2) * (Bc * Dc / 4)];
        float4 v3 = p[(size_t)(l + 3) * (Bc * Dc / 4)];
        float4 v4 = p[(size_t)(l + 4) * (Bc * Dc / 4)];
        float4 v5 = p[(size_t)(l + 5) * (Bc * Dc / 4)];
        float4 v6 = p[(size_t)(l + 6) * (Bc * Dc / 4)];
        float4 v7 = p[(size_t)(l + 7) * (Bc * Dc / 4)];
        a0.x += v0.x; a0.y += v0.y; a0.z += v0.z; a0.w += v0.w;
        a1.x += v1.x; a1.y += v1.y; a1.z += v1.z; a1.w += v1.w;
        a2.x += v2.x; a2.y += v2.y; a2.z += v2.z; a2.w += v2.w;
        a3.x += v3.x; a3.y += v3.y; a3.z += v3.z; a3.w += v3.w;
        a0.x += v4.x; a0.y += v4.y; a0.z += v4.z; a0.w += v4.w;
        a1.x += v5.x; a1.y += v5.y; a1.z += v5.z; a1.w += v5.w;
        a2.x += v6.x; a2.y += v6.y; a2.z += v6.z; a2.w += v6.w;
        a3.x += v7.x; a3.y += v7.y; a3.z += v7.z; a3.w += v7.w;
    }
    float4 r;
    r.x = (a0.x + a1.x) + (a2.x + a3.x);
    r.y = (a0.y + a1.y) + (a2.y + a3.y);
    r.z = (a0.z + a1.z) + (a2.z + a3.z);
    r.w = (a0.w + a1.w) + (a2.w + a3.w);
    ((float4*)g_hbar_part[blockIdx.y])[cg] = r;
}

// ---------------- ctx assembly: grid (Bc, 3). seg 0: hbar; seg 1: prev; seg 2: first ------------
__global__ void k_ctx(const float* __restrict__ ebp, const int* __restrict__ pa) {
    int b = blockIdx.x, seg = blockIdx.y, t = threadIdx.x;
    if (seg == 0) {
        float hs = 0.f;
        #pragma unroll
        for (int c = 0; c < MEAN_CH; c++) hs += g_hbar_part[c][b * Dc + t];
        g_ctx[b * 3 * Dc + t] = hs * (1.0f / Lc);
    } else if (seg == 1) {
        int aL = pa[b * Tc + (Tc - 1)];
        g_ctx[b * 3 * Dc + Dc + t] = ebp[((size_t)aL * Bc + b) * Dc + t];
    } else {
        int a0 = pa[b * Tc];
        g_ctx[b * 3 * Dc + 2 * Dc + t] = ebp[((size_t)a0 * Bc + b) * Dc + t];
    }
}

// ---------------- Fused flash pass: 4x16-row cp.async quarters (R14 verbatim) ----------------
__global__ void __launch_bounds__(256, 2) k_flash(const float* __restrict__ ebp,
                                                  const int* __restrict__ pa) {
    extern __shared__ float smem[];
    float* tile = smem;                       // [64][256]
    float* wsc  = smem + 64 * 256;            // [64][8]
    unsigned* mb = (unsigned*)(wsc + 64 * 8);
    int b = blockIdx.x, cy = blockIdx.y, t = threadIdx.x;
    int warp = t >> 5, lane = t & 31;
    int l0 = cy * 64;

    if (t < 32) mb[t] = 0u;
    int lr = t >> 4, lp = (t & 15) * 16;
    #pragma unroll
    for (int qd = 0; qd < 4; qd++) {
        const float* src = ebp + ((size_t)(l0 + qd * 16 + lr) * Bc + b) * Dc + lp;
        unsigned int sa = (unsigned int)__cvta_generic_to_shared(tile + (qd * 16 + lr) * 256 + lp);
        #pragma unroll
        for (int k = 0; k < 4; k++) cp_async16(sa + k * 16, src + k * 4);
        asm volatile("cp.async.commit_group;");
    }
    __syncthreads();
    if (t < Tc) {
        int a = pa[b * Tc + t];
        atomicOr(&mb[a >> 5], 1u << (a & 31));
    }

    unsigned long long qkp[Hc][4];
    {
        const ulonglong2* qb = (const ulonglong2*)(g_qk + b * Hc * Dc);
        #pragma unroll
        for (int h = 0; h < Hc; h++) {
            ulonglong2 u0 = qb[h * (Dc / 4) + lane * 2];
            ulonglong2 u1 = qb[h * (Dc / 4) + lane * 2 + 1];
            qkp[h][0] = u0.x; qkp[h][1] = u0.y; qkp[h][2] = u1.x; qkp[h][3] = u1.y;
        }
    }

    #pragma unroll
    for (int qd = 0; qd < 4; qd++) {
        if (qd == 0)      asm volatile("cp.async.wait_group 3;" ::: "memory");
        else if (qd == 1) asm volatile("cp.async.wait_group 2;" ::: "memory");
        else if (qd == 2) asm volatile("cp.async.wait_group 1;" ::: "memory");
        else              asm volatile("cp.async.wait_group 0;" ::: "memory");
        __syncthreads();
        #pragma unroll
        for (int j = 0; j < 2; j++) {
            int r = qd * 16 + warp * 2 + j;
            const ulonglong2* rp = (const ulonglong2*)(tile + r * 256) + lane * 2;
            ulonglong2 A = rp[0], B = rp[1];
            unsigned long long e[4] = {A.x, A.y, B.x, B.y};
            float sc[Hc];
            #pragma unroll
            for (int h = 0; h < Hc; h++) {
                unsigned long long acc = 0ull;
                #pragma unroll
                for (int q = 0; q < 4; q++) fma2(acc, e[q], qkp[h][q]);
                float2 f = ull2f2(acc);
                sc[h] = f.x + f.y;
            }
            float v = fold8(sc, lane);
            if ((lane & 3) == 0) {
                int h = lane >> 2;
                int l = l0 + r;
                bool m = (mb[l >> 5] >> (l & 31)) & 1u;
                wsc[r * 8 + h] = m ? -1e4f : v;
            }
        }
    }
    __syncthreads();

    {
        int h = warp;
        float lv0 = wsc[lane * 8 + h];
        float lv1 = wsc[(lane + 32) * 8 + h];
        float m = fmaxf(lv0, lv1);
        #pragma unroll
        for (int o = 16; o > 0; o >>= 1) m = fmaxf(m, __shfl_xor_sync(0xffffffffu, m, o));
        float w0 = __expf(lv0 - m), w1 = __expf(lv1 - m);
        float s = w0 + w1;
        #pragma unroll
        for (int o = 16; o > 0; o >>= 1) s += __shfl_xor_sync(0xffffffffu, s, o);
        wsc[lane * 8 + h] = w0;
        wsc[(lane + 32) * 8 + h] = w1;
        if (lane == 0) g_ms[(b * FL_CH + cy) * Hc + h] = make_float2(m, s);
    }
    __syncthreads();

    unsigned long long acc[4] = {0ull, 0ull, 0ull, 0ull};
    const ulonglong2* wrow = (const ulonglong2*)wsc;
    #pragma unroll 8
    for (int r = 0; r < 64; r++) {
        ulonglong2 w01 = wrow[r * 2];
        ulonglong2 w23 = wrow[r * 2 + 1];
        float e = tile[r * 256 + t];
        unsigned long long ee = f2ull(e, e);
        fma2(acc[0], w01.x, ee);
        fma2(acc[1], w01.y, ee);
        fma2(acc[2], w23.x, ee);
        fma2(acc[3], w23.y, ee);
    }
    #pragma unroll
    for (int hp = 0; hp < 4; hp++) {
        float2 f2v = ull2f2(acc[hp]);
        g_wE_part[cy][(b * Hc + 2 * hp) * Dc + t]     = f2v.x;
        g_wE_part[cy][(b * Hc + 2 * hp + 1) * Dc + t] = f2v.y;
    }
}

// ---------------- combine: wEn[b,h,i] = sum_c wE_part[c]*cf. grid 2048 ----------------
// cf prologue parallelized across 16 threads (one chunk each) + shuffle reductions.
__global__ void k_combine() {
    int bh = blockIdx.x, i = threadIdx.x;
    int b = bh >> 3, h = bh & 7;
    __shared__ float cfs[FL_CH];
    if (i < FL_CH) {
        float2 ms = g_ms[(b * FL_CH + i) * Hc + h];
        float M = ms.x;
        #pragma unroll
        for (int o = 8; o > 0; o >>= 1)
            M = fmaxf(M, __shfl_xor_sync(0x0000ffffu, M, o, 16));
        float ef = __expf(ms.x - M);
        float sv = ms.y * ef;
        #pragma unroll
        for (int o = 8; o > 0; o >>= 1)
            sv += __shfl_xor_sync(0x0000ffffu, sv, o, 16);
        cfs[i] = ef / sv;
    }
    __syncthreads();
    float s = 0.f;
    #pragma unroll
    for (int c = 0; c < FL_CH; c++)
        s += g_wE_part[c][bh * Dc + i] * cfs[c];
    g_wEn[bh * Dc + i] = s;
}

// ---------------- Pass 4a: fs. grid (Bc, 4), register prefetch, fold4 ----------
__global__ void __launch_bounds__(256, 2) k_fs(const float* __restrict__ ebp,
                                               const int* __restrict__ pa) {
    int b = blockIdx.x, t = threadIdx.x;
    int warp = t >> 5, lane = t & 31;
    int l0 = blockIdx.y * 256;
    __shared__ unsigned mbits[32];
    if (t < 32) mbits[t] = 0u;
    __syncthreads();
    if (t < Tc) {
        int a = pa[b * Tc + t];
        atomicOr(&mbits[a >> 5], 1u << (a & 31));
    }
    __syncthreads();
    unsigned long long qp[4];
    {
        const ulonglong2* qb = (const ulonglong2*)(g_qk2 + b * Dc);
        ulonglong2 u0 = qb[lane * 2], u1 = qb[lane * 2 + 1];
        qp[0] = u0.x; qp[1] = u0.y; qp[2] = u1.x; qp[3] = u1.y;
    }
    int base = l0 + warp;
    ulonglong2 cur[4][2], nxt[4][2];
    #pragma unroll
    for (int i = 0; i < 4; i++) {
        const ulonglong2* p = (const ulonglong2*)(ebp + ((size_t)(base + i * 8) * Bc + b) * Dc) + lane * 2;
        cur[i][0] = p[0]; cur[i][1] = p[1];
    }
    #pragma unroll 2
    for (int g = 0; g < 8; g++) {
        if (g < 7) {
            #pragma unroll
            for (int i = 0; i < 4; i++) {
                const ulonglong2* p = (const ulonglong2*)(ebp + ((size_t)(base + ((g + 1) * 4 + i) * 8) * Bc + b) * Dc) + lane * 2;
                nxt[i][0] = p[0]; nxt[i][1] = p[1];
            }
        }
        float r[4];
        #pragma unroll
        for (int i = 0; i < 4; i++) {
            unsigned long long acc = 0ull;
            fma2(acc, cur[i][0].x, qp[0]);
            fma2(acc, cur[i][0].y, qp[1]);
            fma2(acc, cur[i][1].x, qp[2]);
            fma2(acc, cur[i][1].y, qp[3]);
            float2 f = ull2f2(acc);
            r[i] = f.x + f.y;
        }
        float v = fold4(r, lane);
        if ((lane & 7) == 0) {
            int l = base + (g * 4 + (lane >> 3)) * 8;
            bool m = (mbits[l >> 5] >> (l & 31)) & 1u;
            g_fs[b * Lc + l] = m ? -1e30f : tanhf(v) * 10.0f;
        }
        #pragma unroll
        for (int i = 0; i < 4; i++) { cur[i][0] = nxt[i][0]; cur[i][1] = nxt[i][1]; }
    }
}

// ---------------- Pass 4b: per-b softmax over l ----------------
__global__ void k_out(float* __restrict__ out) {
    int b = blockIdx.x, t = threadIdx.x;
    int warp = t >> 5, lane = t & 31;
    __shared__ float red[32];
    float v = g_fs[b * Lc + t];
    float e = __expf(v - 10.0f);
    float sm = e;
    #pragma unroll
    for (int o = 16; o > 0; o >>= 1) sm += __shfl_xor_sync(0xffffffffu, sm, o);
    if (lane == 0) red[warp] = sm;
    __syncthreads();
    if (t < 32) {
        float s = red[t];
        #pragma unroll
        for (int o = 16; o > 0; o >>= 1) s += __shfl_xor_sync(0xffffffffu, s, o);
        red[t] = s;
    }
    __syncthreads();
    out[(size_t)t * Bc + b] = e * (1.0f / red[0]);
}

extern "C" void kernel_launch(void* const* d_in, const int* in_sizes, int n_in,
                              void* d_out, int out_size) {
    const float* ebp = (const float*)d_in[0];
    const int*   pa  = (const int*)d_in[1];
    const float* Wq1 = (const float*)d_in[2];
    const float* Wk1 = (const float*)d_in[3];
    const float* Wv1 = (const float*)d_in[4];
    const float* Wo1 = (const float*)d_in[5];
    const float* Wq2 = (const float*)d_in[6];
    const float* Wk2 = (const float*)d_in[7];
    float* out = (float*)d_out;

    static int init_done = 0;
    static cudaStream_t s2 = nullptr;
    static cudaEvent_t evStart = nullptr, evW = nullptr;
    const int FLASH_SMEM = 64 * 256 * 4 + 64 * 8 * 4 + 128;  // 67712
    if (!init_done) {
        cudaFuncSetAttribute(k_flash, cudaFuncAttributeMaxDynamicSharedMemorySize, FLASH_SMEM);
        cudaStreamCreate(&s2);
        cudaEventCreateWithFlags(&evStart, cudaEventDisableTiming);
        cudaEventCreateWithFlags(&evW, cudaEventDisableTiming);
        init_done = 1;
    }

    float* d_Wt1;    cudaGetSymbolAddress((void**)&d_Wt1,    g_Wt1);
    float* d_Wcombo; cudaGetSymbolAddress((void**)&d_Wcombo, g_Wcombo);
    float* d_wEn;    cudaGetSymbolAddress((void**)&d_wEn,    g_wEn);
    float* d_ho;     cudaGetSymbolAddress((void**)&d_ho,     g_ho);
    float* d_qk2;    cudaGetSymbolAddress((void**)&d_qk2,    g_qk2);

    // ---- fork side stream: precompute Wcombo = (Wo1 @ Wq2 @ Wk2^T)/16 ----
    cudaEventRecord(evStart, 0);
    cudaStreamWaitEvent(s2, evStart, 0);
    k_gemm16<0><<<dim3(16, 8, 1), 128, 0, s2>>>(Wo1, Dc, 0, Wq2, Dc, 0,
                                                d_Wt1, Dc, 0, Dc, 1.0f);
    k_gemm16<1><<<dim3(16, 8, 1), 128, 0, s2>>>(d_Wt1, Dc, 0, Wk2, Dc, 0,
                                                d_Wcombo, Dc, 0, Dc, 1.0f / 16.0f);
    cudaEventRecord(evW, s2);

    // ---- main stream ----
    dim3 gm(64, MEAN_CH);
    k_mean_part<<<gm, 256>>>(ebp);
    k_ctx<<<dim3(Bc, 3), 256>>>(ebp, pa);
    k_q1qk<<<dim3(16, 8), 128>>>(Wq1, Wk1);

    dim3 gf(Bc, FL_CH);
    k_flash<<<gf, 256, FLASH_SMEM>>>(ebp, pa);
    k_combine<<<Bc * Hc, 256>>>();

    // head_out[b, h*32+d] = wEn[b,h,i] . Wv1[i, h*32+d]   (per head, N=32)
    k_gemm16<0><<<dim3(16, 1, Hc), 128>>>(d_wEn, Hc * Dc, Dc, Wv1, Dc, DHc,
                                          d_ho, Dc, DHc, Dc, 1.0f);
    // join side stream, then qk2 = ho @ Wcombo
    cudaStreamWaitEvent(0, evW, 0);
    k_gemm16<0><<<dim3(16, 8, 1), 128>>>(d_ho, Dc, 0, d_Wcombo, Dc, 0,
                                         d_qk2, Dc, 0, Dc, 1.0f);

    dim3 gs(Bc, 4);
    k_fs<<<gs, 256>>>(ebp, pa);
    k_out<<<Bc, 1024>>>(out);
}

// round 17
// speedup vs baseline: 1.0833x; 1.0065x over previous
#include <cuda_runtime.h>

#define Lc 1024
#define Bc 256
#define Dc 256
#define Tc 50
#define Hc 8
#define DHc 32

#define MEAN_CH 16  // L-chunks for mean pass
#define FL_CH 16    // L-chunks for flash pass (64 rows each)

// Scratch (allocation-free rule: __device__ globals)
__device__ float g_hbar_part[MEAN_CH][Bc*Dc];
__device__ float g_ctx[Bc*3*Dc];                // [b][0..767]
__device__ float g_qk[Bc*Hc*Dc];                // [b][h][i], includes 1/sqrt(32)
__device__ float g_wE_part[FL_CH][Bc*Hc*Dc];    // unnormalized partial [b][h][i]
__device__ float2 g_ms[Bc*FL_CH*Hc];            // (m, s) per (b, chunk, h)
__device__ float g_wEn[Bc*Hc*Dc];               // normalized wE
__device__ float g_ho[Bc*Dc];                   // head_out flattened
__device__ float g_qk2[Bc*Dc];                  // includes 1/16
__device__ float g_fs[Bc*Lc];                   // [b][l]
__device__ float g_Wt1[Dc*Dc];                  // Wo1 @ Wq2
__device__ float g_Wcombo[Dc*Dc];               // (Wo1 @ Wq2 @ Wk2^T) / 16

__device__ __forceinline__ unsigned long long f2ull(float x, float y) {
    unsigned long long u;
    asm("mov.b64 %0, {%1,%2};" : "=l"(u) : "f"(x), "f"(y));
    return u;
}
__device__ __forceinline__ float2 ull2f2(unsigned long long u) {
    float2 f;
    asm("mov.b64 {%0,%1}, %2;" : "=f"(f.x), "=f"(f.y) : "l"(u));
    return f;
}
__device__ __forceinline__ void fma2(unsigned long long& acc, unsigned long long a, unsigned long long b) {
    asm("fma.rn.f32x2 %0, %1, %2, %3;" : "=l"(acc) : "l"(a), "l"(b), "l"(acc));
}
__device__ __forceinline__ void cp_async16(unsigned int saddr, const void* g) {
    asm volatile("cp.async.cg.shared.global [%0], [%1], 16;" :: "r"(saddr), "l"(g));
}

// 8-value fold reduction: lanes with lane%4==0 hold full sum for head (lane>>2). 9 shuffles.
__device__ __forceinline__ float fold8(const float sc[8], int lane) {
    bool hi16 = (lane & 16) != 0;
    float n[4];
    #pragma unroll
    for (int k = 0; k < 4; k++) {
        float give = hi16 ? sc[k] : sc[4 + k];
        float keep = hi16 ? sc[4 + k] : sc[k];
        n[k] = keep + __shfl_xor_sync(0xffffffffu, give, 16);
    }
    bool hi8 = (lane & 8) != 0;
    float m[2];
    #pragma unroll
    for (int j = 0; j < 2; j++) {
        float give = hi8 ? n[j] : n[2 + j];
        float keep = hi8 ? n[2 + j] : n[j];
        m[j] = keep + __shfl_xor_sync(0xffffffffu, give, 8);
    }
    bool hi4 = (lane & 4) != 0;
    float give = hi4 ? m[0] : m[1];
    float keep = hi4 ? m[1] : m[0];
    float v = keep + __shfl_xor_sync(0xffffffffu, give, 4);
    v += __shfl_xor_sync(0xffffffffu, v, 1);
    v += __shfl_xor_sync(0xffffffffu, v, 2);
    return v;
}

// 4-value fold: lanes with lane%8==0 hold row (lane>>3).
__device__ __forceinline__ float fold4(const float r[4], int lane) {
    bool hi16 = (lane & 16) != 0;
    float n[2];
    #pragma unroll
    for (int j = 0; j < 2; j++) {
        float give = hi16 ? r[j] : r[2 + j];
        float keep = hi16 ? r[2 + j] : r[j];
        n[j] = keep + __shfl_xor_sync(0xffffffffu, give, 16);
    }
    bool hi8 = (lane & 8) != 0;
    float give = hi8 ? n[0] : n[1];
    float keep = hi8 ? n[1] : n[0];
    float v = keep + __shfl_xor_sync(0xffffffffu, give, 8);
    v += __shfl_xor_sync(0xffffffffu, v, 4);
    v += __shfl_xor_sync(0xffffffffu, v, 2);
    v += __shfl_xor_sync(0xffffffffu, v, 1);
    return v;
}

// ---------------- 16x32-tile GEMM with register-prefetched K-tiles, 128 threads ----------------
template<int TRANSB>
__global__ void __launch_bounds__(128) k_gemm16(const float* __restrict__ A, int lda, int aSz,
                                                const float* __restrict__ B, int ldb, int bSz,
                                                float* __restrict__ C, int ldc, int cSz,
                                                int K, float alpha) {
    __shared__ float As[32][18];
    __shared__ float Bs[32][34];
    int t = threadIdx.x;
    const float* Ab = A + (size_t)blockIdx.z * aSz + (size_t)(blockIdx.x * 16) * lda;
    const float* Bb = TRANSB ? (B + (size_t)blockIdx.z * bSz + (size_t)(blockIdx.y * 32) * ldb)
                             : (B + (size_t)blockIdx.z * bSz + blockIdx.y * 32);
    float* Cb = C + (size_t)blockIdx.z * cSz + (size_t)(blockIdx.x * 16) * ldc + blockIdx.y * 32;
    int ty = t >> 4, tx = t & 15;
    int r = t >> 3, q = (t & 7) * 4;
    float a00 = 0.f, a01 = 0.f, a10 = 0.f, a11 = 0.f;

    float4 av, bv0, bv1;
    av = *(const float4*)(Ab + (size_t)r * lda + q);
    bv0 = *(const float4*)(Bb + (size_t)r * ldb + q);
    bv1 = *(const float4*)(Bb + (size_t)(r + 16) * ldb + q);
    int nk = K / 32;
    for (int kt = 0; kt < nk; kt++) {
        As[q + 0][r] = av.x; As[q + 1][r] = av.y; As[q + 2][r] = av.z; As[q + 3][r] = av.w;
        if (TRANSB) {
            Bs[q + 0][r] = bv0.x; Bs[q + 1][r] = bv0.y; Bs[q + 2][r] = bv0.z; Bs[q + 3][r] = bv0.w;
            Bs[q + 0][r + 16] = bv1.x; Bs[q + 1][r + 16] = bv1.y; Bs[q + 2][r + 16] = bv1.z; Bs[q + 3][r + 16] = bv1.w;
        } else {
            Bs[r][q + 0] = bv0.x; Bs[r][q + 1] = bv0.y; Bs[r][q + 2] = bv0.z; Bs[r][q + 3] = bv0.w;
            Bs[r + 16][q + 0] = bv1.x; Bs[r + 16][q + 1] = bv1.y; Bs[r + 16][q + 2] = bv1.z; Bs[r + 16][q + 3] = bv1.w;
        }
        __syncthreads();
        if (kt + 1 < nk) {
            int k0 = (kt + 1) * 32;
            av = *(const float4*)(Ab + (size_t)r * lda + k0 + q);
            if (TRANSB) {
                bv0 = *(const float4*)(Bb + (size_t)r * ldb + k0 + q);
                bv1 = *(const float4*)(Bb + (size_t)(r + 16) * ldb + k0 + q);
            } else {
                bv0 = *(const float4*)(Bb + (size_t)(k0 + r) * ldb + q);
                bv1 = *(const float4*)(Bb + (size_t)(k0 + r + 16) * ldb + q);
            }
        }
        #pragma unroll
        for (int k = 0; k < 32; k++) {
            float2 a = *(const float2*)&As[k][ty * 2];
            float2 b = *(const float2*)&Bs[k][tx * 2];
            a00 = fmaf(a.x, b.x, a00); a01 = fmaf(a.x, b.y, a01);
            a10 = fmaf(a.y, b.x, a10); a11 = fmaf(a.y, b.y, a11);
        }
        __syncthreads();
    }
    Cb[(size_t)(ty * 2) * ldc + tx * 2]     = alpha * a00;
    Cb[(size_t)(ty * 2) * ldc + tx * 2 + 1] = alpha * a01;
    Cb[(size_t)(ty * 2 + 1) * ldc + tx * 2]     = alpha * a10;
    Cb[(size_t)(ty * 2 + 1) * ldc + tx * 2 + 1] = alpha * a11;
}

// ---------------- Fused q1+qk: grid (16 b-tiles, 8 heads), 128 threads ----------------
__global__ void __launch_bounds__(128) k_q1qk(const float* __restrict__ Wq1,
                                              const float* __restrict__ Wk1) {
    __shared__ float As[32][18];
    __shared__ float Bs[32][34];
    __shared__ __align__(16) float q1s[16][36];
    int t = threadIdx.x;
    int bx = blockIdx.x, h = blockIdx.y;
    const int LDA = 3 * Dc;
    const float* Ab = g_ctx + (size_t)(bx * 16) * LDA;
    const float* Bb = Wq1 + h * 32;
    int ty = t >> 4, tx = t & 15;
    int r = t >> 3, q = (t & 7) * 4;
    float a00 = 0.f, a01 = 0.f, a10 = 0.f, a11 = 0.f;

    float4 av  = *(const float4*)(Ab + (size_t)r * LDA + q);
    float4 bv0 = *(const float4*)(Bb + (size_t)r * Dc + q);
    float4 bv1 = *(const float4*)(Bb + (size_t)(r + 16) * Dc + q);
    const int nk = LDA / 32;
    for (int kt = 0; kt < nk; kt++) {
        As[q + 0][r] = av.x; As[q + 1][r] = av.y; As[q + 2][r] = av.z; As[q + 3][r] = av.w;
        Bs[r][q + 0] = bv0.x; Bs[r][q + 1] = bv0.y; Bs[r][q + 2] = bv0.z; Bs[r][q + 3] = bv0.w;
        Bs[r + 16][q + 0] = bv1.x; Bs[r + 16][q + 1] = bv1.y; Bs[r + 16][q + 2] = bv1.z; Bs[r + 16][q + 3] = bv1.w;
        __syncthreads();
        if (kt + 1 < nk) {
            int k0 = (kt + 1) * 32;
            av  = *(const float4*)(Ab + (size_t)r * LDA + k0 + q);
            bv0 = *(const float4*)(Bb + (size_t)(k0 + r) * Dc + q);
            bv1 = *(const float4*)(Bb + (size_t)(k0 + r + 16) * Dc + q);
        }
        #pragma unroll
        for (int k = 0; k < 32; k++) {
            float2 a = *(const float2*)&As[k][ty * 2];
            float2 b = *(const float2*)&Bs[k][tx * 2];
            a00 = fmaf(a.x, b.x, a00); a01 = fmaf(a.x, b.y, a01);
            a10 = fmaf(a.y, b.x, a10); a11 = fmaf(a.y, b.y, a11);
        }
        __syncthreads();
    }
    q1s[ty * 2][tx * 2]     = a00;
    q1s[ty * 2][tx * 2 + 1] = a01;
    q1s[ty * 2 + 1][tx * 2]     = a10;
    q1s[ty * 2 + 1][tx * 2 + 1] = a11;
    __syncthreads();

    int bhalf = t >> 6, ig = t & 63;
    const float* wbase = Wk1 + (size_t)(ig * 4) * Dc + h * 32;
    #pragma unroll 2
    for (int bb = 0; bb < 8; bb++) {
        int bloc = bhalf * 8 + bb;
        float s0 = 0.f, s1 = 0.f, s2 = 0.f, s3 = 0.f;
        #pragma unroll
        for (int dq = 0; dq < 8; dq++) {
            float4 qv = *(const float4*)&q1s[bloc][dq * 4];
            float4 w0 = *(const float4*)(wbase + 0 * Dc + dq * 4);
            float4 w1 = *(const float4*)(wbase + 1 * Dc + dq * 4);
            float4 w2 = *(const float4*)(wbase + 2 * Dc + dq * 4);
            float4 w3 = *(const float4*)(wbase + 3 * Dc + dq * 4);
            s0 += qv.x * w0.x + qv.y * w0.y + qv.z * w0.z + qv.w * w0.w;
            s1 += qv.x * w1.x + qv.y * w1.y + qv.z * w1.z + qv.w * w1.w;
            s2 += qv.x * w2.x + qv.y * w2.y + qv.z * w2.z + qv.w * w2.w;
            s3 += qv.x * w3.x + qv.y * w3.y + qv.z * w3.z + qv.w * w3.w;
        }
        const float sc = 0.17677669529663687f;
        float4 o = make_float4(s0 * sc, s1 * sc, s2 * sc, s3 * sc);
        *(float4*)&g_qk[(((size_t)(bx * 16 + bloc)) * Hc + h) * Dc + ig * 4] = o;
    }
}

// ---------------- Pass 1: partial sums for hbar. grid (64, MEAN_CH), block 256 ----------------
__global__ void k_mean_part(const float* __restrict__ ebp) {
    int cg = blockIdx.x * 256 + threadIdx.x;
    int l0 = blockIdx.y * (Lc / MEAN_CH);
    const float4* p = (const float4*)ebp + (size_t)l0 * (Bc * Dc / 4) + cg;
    float4 a0 = {0,0,0,0}, a1 = {0,0,0,0}, a2 = {0,0,0,0}, a3 = {0,0,0,0};
    #pragma unroll 2
    for (int l = 0; l < Lc / MEAN_CH; l += 8) {
        float4 v0 = p[(size_t)(l + 0) * (Bc * Dc / 4)];
        float4 v1 = p[(size_t)(l + 1) * (Bc * Dc / 4)];
        float4 v2 = p[(size_t)(l + 2) * (Bc * Dc / 4)];
        float4 v3 = p[(size_t)(l + 3) * (Bc * Dc / 4)];
        float4 v4 = p[(size_t)(l + 4) * (Bc * Dc / 4)];
        float4 v5 = p[(size_t)(l + 5) * (Bc * Dc / 4)];
        float4 v6 = p[(size_t)(l + 6) * (Bc * Dc / 4)];
        float4 v7 = p[(size_t)(l + 7) * (Bc * Dc / 4)];
        a0.x += v0.x; a0.y += v0.y; a0.z += v0.z; a0.w += v0.w;
        a1.x += v1.x; a1.y += v1.y; a1.z += v1.z; a1.w += v1.w;
        a2.x += v2.x; a2.y += v2.y; a2.z += v2.z; a2.w += v2.w;
        a3.x += v3.x; a3.y += v3.y; a3.z += v3.z; a3.w += v3.w;
        a0.x += v4.x; a0.y += v4.y; a0.z += v4.z; a0.w += v4.w;
        a1.x += v5.x; a1.y += v5.y; a1.z += v5.z; a1.w += v5.w;
        a2.x += v6.x; a2.y += v6.y; a2.z += v6.z; a2.w += v6.w;
        a3.x += v7.x; a3.y += v7.y; a3.z += v7.z; a3.w += v7.w;
    }
    float4 r;
    r.x = (a0.x + a1.x) + (a2.x + a3.x);
    r.y = (a0.y + a1.y) + (a2.y + a3.y);
    r.z = (a0.z + a1.z) + (a2.z + a3.z);
    r.w = (a0.w + a1.w) + (a2.w + a3.w);
    ((float4*)g_hbar_part[blockIdx.y])[cg] = r;
}

// ---------------- ctx gather (segs 1,2) — independent of mean, runs on side stream ----------
__global__ void k_ctx_gather(const float* __restrict__ ebp, const int* __restrict__ pa) {
    int b = blockIdx.x, seg = blockIdx.y, t = threadIdx.x;
    if (seg == 0) {
        int aL = pa[b * Tc + (Tc - 1)];
        g_ctx[b * 3 * Dc + Dc + t] = ebp[((size_t)aL * Bc + b) * Dc + t];
    } else {
        int a0 = pa[b * Tc];
        g_ctx[b * 3 * Dc + 2 * Dc + t] = ebp[((size_t)a0 * Bc + b) * Dc + t];
    }
}

// ---------------- ctx hbar segment — after mean ----------------
__global__ void k_ctx_hbar() {
    int b = blockIdx.x, t = threadIdx.x;
    float hs = 0.f;
    #pragma unroll
    for (int c = 0; c < MEAN_CH; c++) hs += g_hbar_part[c][b * Dc + t];
    g_ctx[b * 3 * Dc + t] = hs * (1.0f / Lc);
}

// ---------------- Fused flash pass: 4x16-row cp.async quarters (R14 verbatim) ----------------
__global__ void __launch_bounds__(256, 2) k_flash(const float* __restrict__ ebp,
                                                  const int* __restrict__ pa) {
    extern __shared__ float smem[];
    float* tile = smem;                       // [64][256]
    float* wsc  = smem + 64 * 256;            // [64][8]
    unsigned* mb = (unsigned*)(wsc + 64 * 8);
    int b = blockIdx.x, cy = blockIdx.y, t = threadIdx.x;
    int warp = t >> 5, lane = t & 31;
    int l0 = cy * 64;

    if (t < 32) mb[t] = 0u;
    int lr = t >> 4, lp = (t & 15) * 16;
    #pragma unroll
    for (int qd = 0; qd < 4; qd++) {
        const float* src = ebp + ((size_t)(l0 + qd * 16 + lr) * Bc + b) * Dc + lp;
        unsigned int sa = (unsigned int)__cvta_generic_to_shared(tile + (qd * 16 + lr) * 256 + lp);
        #pragma unroll
        for (int k = 0; k < 4; k++) cp_async16(sa + k * 16, src + k * 4);
        asm volatile("cp.async.commit_group;");
    }
    __syncthreads();
    if (t < Tc) {
        int a = pa[b * Tc + t];
        atomicOr(&mb[a >> 5], 1u << (a & 31));
    }

    unsigned long long qkp[Hc][4];
    {
        const ulonglong2* qb = (const ulonglong2*)(g_qk + b * Hc * Dc);
        #pragma unroll
        for (int h = 0; h < Hc; h++) {
            ulonglong2 u0 = qb[h * (Dc / 4) + lane * 2];
            ulonglong2 u1 = qb[h * (Dc / 4) + lane * 2 + 1];
            qkp[h][0] = u0.x; qkp[h][1] = u0.y; qkp[h][2] = u1.x; qkp[h][3] = u1.y;
        }
    }

    #pragma unroll
    for (int qd = 0; qd < 4; qd++) {
        if (qd == 0)      asm volatile("cp.async.wait_group 3;" ::: "memory");
        else if (qd == 1) asm volatile("cp.async.wait_group 2;" ::: "memory");
        else if (qd == 2) asm volatile("cp.async.wait_group 1;" ::: "memory");
        else              asm volatile("cp.async.wait_group 0;" ::: "memory");
        __syncthreads();
        #pragma unroll
        for (int j = 0; j < 2; j++) {
            int r = qd * 16 + warp * 2 + j;
            const ulonglong2* rp = (const ulonglong2*)(tile + r * 256) + lane * 2;
            ulonglong2 A = rp[0], B = rp[1];
            unsigned long long e[4] = {A.x, A.y, B.x, B.y};
            float sc[Hc];
            #pragma unroll
            for (int h = 0; h < Hc; h++) {
                unsigned long long acc = 0ull;
                #pragma unroll
                for (int q = 0; q < 4; q++) fma2(acc, e[q], qkp[h][q]);
                float2 f = ull2f2(acc);
                sc[h] = f.x + f.y;
            }
            float v = fold8(sc, lane);
            if ((lane & 3) == 0) {
                int h = lane >> 2;
                int l = l0 + r;
                bool m = (mb[l >> 5] >> (l & 31)) & 1u;
                wsc[r * 8 + h] = m ? -1e4f : v;
            }
        }
    }
    __syncthreads();

    {
        int h = warp;
        float lv0 = wsc[lane * 8 + h];
        float lv1 = wsc[(lane + 32) * 8 + h];
        float m = fmaxf(lv0, lv1);
        #pragma unroll
        for (int o = 16; o > 0; o >>= 1) m = fmaxf(m, __shfl_xor_sync(0xffffffffu, m, o));
        float w0 = __expf(lv0 - m), w1 = __expf(lv1 - m);
        float s = w0 + w1;
        #pragma unroll
        for (int o = 16; o > 0; o >>= 1) s += __shfl_xor_sync(0xffffffffu, s, o);
        wsc[lane * 8 + h] = w0;
        wsc[(lane + 32) * 8 + h] = w1;
        if (lane == 0) g_ms[(b * FL_CH + cy) * Hc + h] = make_float2(m, s);
    }
    __syncthreads();

    unsigned long long acc[4] = {0ull, 0ull, 0ull, 0ull};
    const ulonglong2* wrow = (const ulonglong2*)wsc;
    #pragma unroll 8
    for (int r = 0; r < 64; r++) {
        ulonglong2 w01 = wrow[r * 2];
        ulonglong2 w23 = wrow[r * 2 + 1];
        float e = tile[r * 256 + t];
        unsigned long long ee = f2ull(e, e);
        fma2(acc[0], w01.x, ee);
        fma2(acc[1], w01.y, ee);
        fma2(acc[2], w23.x, ee);
        fma2(acc[3], w23.y, ee);
    }
    #pragma unroll
    for (int hp = 0; hp < 4; hp++) {
        float2 f2v = ull2f2(acc[hp]);
        g_wE_part[cy][(b * Hc + 2 * hp) * Dc + t]     = f2v.x;
        g_wE_part[cy][(b * Hc + 2 * hp + 1) * Dc + t] = f2v.y;
    }
}

// ---------------- combine: wEn[b,h,i] = sum_c wE_part[c]*cf. grid 2048 ----------------
__global__ void k_combine() {
    int bh = blockIdx.x, i = threadIdx.x;
    int b = bh >> 3, h = bh & 7;
    __shared__ float cfs[FL_CH];
    if (i < FL_CH) {
        float2 ms = g_ms[(b * FL_CH + i) * Hc + h];
        float M = ms.x;
        #pragma unroll
        for (int o = 8; o > 0; o >>= 1)
            M = fmaxf(M, __shfl_xor_sync(0x0000ffffu, M, o, 16));
        float ef = __expf(ms.x - M);
        float sv = ms.y * ef;
        #pragma unroll
        for (int o = 8; o > 0; o >>= 1)
            sv += __shfl_xor_sync(0x0000ffffu, sv, o, 16);
        cfs[i] = ef / sv;
    }
    __syncthreads();
    float s = 0.f;
    #pragma unroll
    for (int c = 0; c < FL_CH; c++)
        s += g_wE_part[c][bh * Dc + i] * cfs[c];
    g_wEn[bh * Dc + i] = s;
}

// ---------------- Pass 4a: fs. grid (Bc, 8): 128 rows/block, register prefetch, fold4 ----------
__global__ void __launch_bounds__(256, 2) k_fs(const float* __restrict__ ebp,
                                               const int* __restrict__ pa) {
    int b = blockIdx.x, t = threadIdx.x;
    int warp = t >> 5, lane = t & 31;
    int l0 = blockIdx.y * 128;
    __shared__ unsigned mbits[32];
    if (t < 32) mbits[t] = 0u;
    __syncthreads();
    if (t < Tc) {
        int a = pa[b * Tc + t];
        atomicOr(&mbits[a >> 5], 1u << (a & 31));
    }
    __syncthreads();
    unsigned long long qp[4];
    {
        const ulonglong2* qb = (const ulonglong2*)(g_qk2 + b * Dc);
        ulonglong2 u0 = qb[lane * 2], u1 = qb[lane * 2 + 1];
        qp[0] = u0.x; qp[1] = u0.y; qp[2] = u1.x; qp[3] = u1.y;
    }
    int base = l0 + warp;
    ulonglong2 cur[4][2], nxt[4][2];
    #pragma unroll
    for (int i = 0; i < 4; i++) {
        const ulonglong2* p = (const ulonglong2*)(ebp + ((size_t)(base + i * 8) * Bc + b) * Dc) + lane * 2;
        cur[i][0] = p[0]; cur[i][1] = p[1];
    }
    #pragma unroll
    for (int g = 0; g < 4; g++) {
        if (g < 3) {
            #pragma unroll
            for (int i = 0; i < 4; i++) {
                const ulonglong2* p = (const ulonglong2*)(ebp + ((size_t)(base + ((g + 1) * 4 + i) * 8) * Bc + b) * Dc) + lane * 2;
                nxt[i][0] = p[0]; nxt[i][1] = p[1];
            }
        }
        float r[4];
        #pragma unroll
        for (int i = 0; i < 4; i++) {
            unsigned long long acc = 0ull;
            fma2(acc, cur[i][0].x, qp[0]);
            fma2(acc, cur[i][0].y, qp[1]);
            fma2(acc, cur[i][1].x, qp[2]);
            fma2(acc, cur[i][1].y, qp[3]);
            float2 f = ull2f2(acc);
            r[i] = f.x + f.y;
        }
        float v = fold4(r, lane);
        if ((lane & 7) == 0) {
            int l = base + (g * 4 + (lane >> 3)) * 8;
            bool m = (mbits[l >> 5] >> (l & 31)) & 1u;
            g_fs[b * Lc + l] = m ? -1e30f : tanhf(v) * 10.0f;
        }
        #pragma unroll
        for (int i = 0; i < 4; i++) { cur[i][0] = nxt[i][0]; cur[i][1] = nxt[i][1]; }
    }
}

// ---------------- Pass 4b: per-b softmax over l ----------------
__global__ void k_out(float* __restrict__ out) {
    int b = blockIdx.x, t = threadIdx.x;
    int warp = t >> 5, lane = t & 31;
    __shared__ float red[32];
    float v = g_fs[b * Lc + t];
    float e = __expf(v - 10.0f);
    float sm = e;
    #pragma unroll
    for (int o = 16; o > 0; o >>= 1) sm += __shfl_xor_sync(0xffffffffu, sm, o);
    if (lane == 0) red[warp] = sm;
    __syncthreads();
    if (t < 32) {
        float s = red[t];
        #pragma unroll
        for (int o = 16; o > 0; o >>= 1) s += __shfl_xor_sync(0xffffffffu, s, o);
        red[t] = s;
    }
    __syncthreads();
    out[(size_t)t * Bc + b] = e * (1.0f / red[0]);
}

extern "C" void kernel_launch(void* const* d_in, const int* in_sizes, int n_in,
                              void* d_out, int out_size) {
    const float* ebp = (const float*)d_in[0];
    const int*   pa  = (const int*)d_in[1];
    const float* Wq1 = (const float*)d_in[2];
    const float* Wk1 = (const float*)d_in[3];
    const float* Wv1 = (const float*)d_in[4];
    const float* Wo1 = (const float*)d_in[5];
    const float* Wq2 = (const float*)d_in[6];
    const float* Wk2 = (const float*)d_in[7];
    float* out = (float*)d_out;

    static int init_done = 0;
    static cudaStream_t s2 = nullptr;
    static cudaEvent_t evStart = nullptr, evW = nullptr, evG = nullptr;
    const int FLASH_SMEM = 64 * 256 * 4 + 64 * 8 * 4 + 128;  // 67712
    if (!init_done) {
        cudaFuncSetAttribute(k_flash, cudaFuncAttributeMaxDynamicSharedMemorySize, FLASH_SMEM);
        cudaStreamCreate(&s2);
        cudaEventCreateWithFlags(&evStart, cudaEventDisableTiming);
        cudaEventCreateWithFlags(&evW, cudaEventDisableTiming);
        cudaEventCreateWithFlags(&evG, cudaEventDisableTiming);
        init_done = 1;
    }

    float* d_Wt1;    cudaGetSymbolAddress((void**)&d_Wt1,    g_Wt1);
    float* d_Wcombo; cudaGetSymbolAddress((void**)&d_Wcombo, g_Wcombo);
    float* d_wEn;    cudaGetSymbolAddress((void**)&d_wEn,    g_wEn);
    float* d_ho;     cudaGetSymbolAddress((void**)&d_ho,     g_ho);
    float* d_qk2;    cudaGetSymbolAddress((void**)&d_qk2,    g_qk2);

    // ---- fork side stream: ctx gathers (indep of mean) + Wcombo precompute ----
    cudaEventRecord(evStart, 0);
    cudaStreamWaitEvent(s2, evStart, 0);
    k_ctx_gather<<<dim3(Bc, 2), 256, 0, s2>>>(ebp, pa);
    cudaEventRecord(evG, s2);
    k_gemm16<0><<<dim3(16, 8, 1), 128, 0, s2>>>(Wo1, Dc, 0, Wq2, Dc, 0,
                                                d_Wt1, Dc, 0, Dc, 1.0f);
    k_gemm16<1><<<dim3(16, 8, 1), 128, 0, s2>>>(d_Wt1, Dc, 0, Wk2, Dc, 0,
                                                d_Wcombo, Dc, 0, Dc, 1.0f / 16.0f);
    cudaEventRecord(evW, s2);

    // ---- main stream ----
    dim3 gm(64, MEAN_CH);
    k_mean_part<<<gm, 256>>>(ebp);
    k_ctx_hbar<<<Bc, 256>>>();
    cudaStreamWaitEvent(0, evG, 0);
    k_q1qk<<<dim3(16, 8), 128>>>(Wq1, Wk1);

    dim3 gf(Bc, FL_CH);
    k_flash<<<gf, 256, FLASH_SMEM>>>(ebp, pa);
    k_combine<<<Bc * Hc, 256>>>();

    // head_out[b, h*32+d] = wEn[b,h,i] . Wv1[i, h*32+d]   (per head, N=32)
    k_gemm16<0><<<dim3(16, 1, Hc), 128>>>(d_wEn, Hc * Dc, Dc, Wv1, Dc, DHc,
                                          d_ho, Dc, DHc, Dc, 1.0f);
    // join side stream, then qk2 = ho @ Wcombo
    cudaStreamWaitEvent(0, evW, 0);
    k_gemm16<0><<<dim3(16, 8, 1), 128>>>(d_ho, Dc, 0, d_Wcombo, Dc, 0,
                                         d_qk2, Dc, 0, Dc, 1.0f);

    dim3 gs(Bc, 8);
    k_fs<<<gs, 256>>>(ebp, pa);
    k_out<<<Bc, 1024>>>(out);
}